// round 8
// baseline (speedup 1.0000x reference)
#include <cuda_runtime.h>
#include <cuda_bf16.h>

// Problem constants (fixed by the reference)
#define PB 64
#define PT 512
#define PD 1024
#define TS 16                 // t-interleave stride / blocks per (b, d-half)
#define NCONTRIB (2 * TS)     // 32 contributor blocks per b

// Zero-invariant scratch: statically zero-initialized at module load; the
// per-b finalizer restores zeros after consuming, so every kernel_launch call
// (correctness run + each graph replay) sees zeros.
__device__ float    g_S  [PB * PD];  // unnormalized s[b,d]
__device__ float    g_YH [PB * PD];  // unnormalized y_hat[b,d]
__device__ unsigned g_cnt[PB];       // per-b arrival counters

// ---------------------------------------------------------------------------
// Single fused kernel. grid (2, TS+1, PB), block 128.
//   by <  TS : contributor — handles rows t = by, by+16, by+32, ... (< L),
//              i.e. an interleaved 1/16 share of the valid range, so work per
//              block is proportional to L (balanced across the whole grid).
//              Partial sums -> atomicAdd into g_S/g_YH, then ONE
//              release-increment of g_cnt[b] by thread 0.
//   by == TS, bx == 0 : finalizer for b — acquire-spin until all 32
//              contributors arrived, then L1-norm + outputs + scratch reset.
// ---------------------------------------------------------------------------
__global__ void __launch_bounds__(128)
k_fused(const float* __restrict__ vs,
        const int*   __restrict__ len,
        const int*   __restrict__ word,
        const float* __restrict__ weights,
        float*       __restrict__ out)
{
    const int b = blockIdx.z;

    if (blockIdx.y == TS) {
        if (blockIdx.x != 0) return;
        // ---------------- finalizer for batch b ----------------
        unsigned* cnt = &g_cnt[b];
        if (threadIdx.x == 0) {
            unsigned v;
            for (;;) {
                asm volatile("ld.acquire.gpu.global.u32 %0, [%1];"
                             : "=r"(v) : "l"(cnt) : "memory");
                if (v >= NCONTRIB) break;
                __nanosleep(64);
            }
            *cnt = 0;  // reset for next replay (kernel-boundary ordering)
        }
        __syncthreads();

        const int tid = threadIdx.x;
        float4* sB = reinterpret_cast<float4*>(g_S  + (size_t)b * PD);
        float4* hB = reinterpret_cast<float4*>(g_YH + (size_t)b * PD);

        float4 s[2], h[2];
#pragma unroll
        for (int j = 0; j < 2; ++j) {
            s[j] = __ldcg(sB + tid + 128 * j);
            h[j] = __ldcg(hB + tid + 128 * j);
        }

        float part = 0.f;
#pragma unroll
        for (int j = 0; j < 2; ++j)
            part += fabsf(s[j].x) + fabsf(s[j].y) + fabsf(s[j].z) + fabsf(s[j].w);

#pragma unroll
        for (int o = 16; o > 0; o >>= 1)
            part += __shfl_xor_sync(0xFFFFFFFFu, part, o);

        __shared__ float sm[4];
        if ((tid & 31) == 0) sm[tid >> 5] = part;
        __syncthreads();
        float tot = sm[0] + sm[1] + sm[2] + sm[3];

        const float r = rsqrtf(tot);

        float4* outY = reinterpret_cast<float4*>(out + (size_t)b * PD);
        float4* outH = reinterpret_cast<float4*>(out + (size_t)(PB + b) * PD);
        const float4 z = make_float4(0.f, 0.f, 0.f, 0.f);
#pragma unroll
        for (int j = 0; j < 2; ++j) {
            outY[tid + 128 * j] =
                make_float4(s[j].x * r, s[j].y * r, s[j].z * r, s[j].w * r);
            outH[tid + 128 * j] = h[j];
            sB[tid + 128 * j] = z;   // restore zero-invariant
            hB[tid + 128 * j] = z;
        }
        return;
    }

    // ---------------- contributor ----------------
    const int L  = __ldg(len + b);
    const int by = blockIdx.y;
    // rows handled: t = by + TS*i for i in [0, n)
    const int n  = (by < L) ? ((L - by + TS - 1) >> 4) : 0;

    if (n > 0) {
        // Warp-wide weight gather: lane i holds weights[word[b, by + TS*i]]
        // (index by + 16*31 <= 511, always in-bounds; values beyond n unused).
        const int   lane  = threadIdx.x & 31;
        const float wlane = weights[word[b * PT + by + TS * lane]];

        const int d0 = blockIdx.x * 512 + threadIdx.x * 4;

        const float4* __restrict__ p =
            reinterpret_cast<const float4*>(vs + ((size_t)b * PT + by) * PD + d0);
        const size_t stride = (size_t)TS * (PD / 4);   // 16 rows per step

        float4 acc  = make_float4(0.f, 0.f, 0.f, 0.f);
        float4 accw = make_float4(0.f, 0.f, 0.f, 0.f);

#pragma unroll 4
        for (int i = 0; i < n; ++i) {
            const float4 v = p[(size_t)i * stride];
            const float  w = __shfl_sync(0xFFFFFFFFu, wlane, i);
            acc.x  += v.x;      acc.y  += v.y;      acc.z  += v.z;      acc.w  += v.w;
            accw.x += w * v.x;  accw.y += w * v.y;  accw.z += w * v.z;  accw.w += w * v.w;
        }

        float* sp = g_S + (size_t)b * PD + d0;
        atomicAdd(sp + 0, acc.x);
        atomicAdd(sp + 1, acc.y);
        atomicAdd(sp + 2, acc.z);
        atomicAdd(sp + 3, acc.w);

        float* yp = g_YH + (size_t)b * PD + d0;
        atomicAdd(yp + 0, accw.x);
        atomicAdd(yp + 1, accw.y);
        atomicAdd(yp + 2, accw.z);
        atomicAdd(yp + 3, accw.w);
    }

    // Arrival: CTA barrier (happens-before from all threads to thread 0),
    // then a single gpu-scope release increment. Cumulativity makes every
    // thread's atomics visible to the finalizer's acquire.
    __syncthreads();
    if (threadIdx.x == 0) {
        asm volatile("red.release.gpu.global.add.u32 [%0], %1;"
                     :: "l"(&g_cnt[b]), "r"(1u) : "memory");
    }
}

// ---------------------------------------------------------------------------
// Entry point: one kernel, one launch.
// ---------------------------------------------------------------------------
extern "C" void kernel_launch(void* const* d_in, const int* in_sizes, int n_in,
                              void* d_out, int out_size)
{
    const float* vs      = (const float*)d_in[0];  // [B,T,D] f32
    const int*   len     = (const int*)  d_in[1];  // [B]
    const int*   word    = (const int*)  d_in[2];  // [B,T]
    const float* weights = (const float*)d_in[3];  // [VOCAB]

    float* out = (float*)d_out;  // y at [0, B*D), y_hat at [B*D, 2*B*D)

    k_fused<<<dim3(2, TS + 1, PB), 128>>>(vs, len, word, weights, out);
}